// round 10
// baseline (speedup 1.0000x reference)
#include <cuda_runtime.h>
#include <cstdint>

// ---------------------------------------------------------------------------
// GenAttentionMask (float32 output: 1.0f / 0.0f):
//   for b in range(batch):
//     s = seq_lengths[b]
//     out += head_num copies of (fp16(mask[b,0,:s,:s]) > 0.5) as float32
//
// fp16_rn(x) > 0.5  <=>  x > 0.500244140625f   (fp16 midpoint, ties-to-even)
//
// Structure: head folded into blockIdx.x (8 consecutive blocks = 8 heads of
// the same input chunk). One load + one store per thread -> each warp emits a
// single contiguous write stream; sibling blocks re-read the same input chunk
// from L2. Tests whether concurrent-write-stream count was capping DRAM%.
// ---------------------------------------------------------------------------

#define MAX_BATCH 16
#define THRESH 0.500244140625f
#define CHUNK_ELEMS 1024           // elements per (block, head): 256 thr * 4

struct Meta {
    int       sl[MAX_BATCH];
    long long outbase[MAX_BATCH];   // element offset of batch b's output region
    int       hn;
};

__device__ Meta g_meta;

__global__ void setup_kernel(const int* __restrict__ sl, const int* __restrict__ hn_ptr, int batch) {
    int hn = hn_ptr ? *hn_ptr : 8;
    if (hn <= 0 || hn > 64) hn = 8;   // sanity clamp
    g_meta.hn = hn;
    long long acc = 0;
    for (int b = 0; b < batch && b < MAX_BATCH; ++b) {
        int s = sl[b];
        g_meta.sl[b] = s;
        g_meta.outbase[b] = acc;
        acc += (long long)hn * (long long)s * (long long)s;
    }
}

__device__ __forceinline__ float4 thresh4(float4 f) {
    float4 v;
    v.x = (f.x > THRESH) ? 1.0f : 0.0f;
    v.y = (f.y > THRESH) ? 1.0f : 0.0f;
    v.z = (f.z > THRESH) ? 1.0f : 0.0f;
    v.w = (f.w > THRESH) ? 1.0f : 0.0f;
    return v;
}

// blockIdx.x = chunk*8 + head_lane ; blockIdx.y = batch.
// Thread handles one float4 at flat offset o within the s*s block, for heads
// head_lane, head_lane+8, ... (< hn).
__global__ void __launch_bounds__(256)
genmask_kernel(const float* __restrict__ in, float* __restrict__ out, int max_seq) {
    const int b = blockIdx.y;
    const int s = g_meta.sl[b];

    const unsigned bx    = blockIdx.x;
    const unsigned chunk = bx >> 3;
    const int      hl    = bx & 7;

    const unsigned o = chunk * CHUNK_ELEMS + threadIdx.x * 4;   // flat in s*s
    const unsigned ssq = (unsigned)s * (unsigned)s;
    if (o >= ssq) return;

    // s is a multiple of 256, so a float4 never straddles a row.
    const unsigned row = o / (unsigned)s;
    const unsigned col = o - row * (unsigned)s;

    const float4 f = *reinterpret_cast<const float4*>(
        in + (size_t)b * max_seq * max_seq + (size_t)row * max_seq + col);
    const float4 v = thresh4(f);

    const int hn = g_meta.hn;
    float* ob = out + (size_t)g_meta.outbase[b] + o;
    for (int h = hl; h < hn; h += 8)
        __stcs(reinterpret_cast<float4*>(ob + (size_t)h * ssq), v);
}

extern "C" void kernel_launch(void* const* d_in, const int* in_sizes, int n_in,
                              void* d_out, int out_size) {
    // Identify inputs by size, not position:
    //   mask        = largest input
    //   head_num    = 1-element input
    //   seq_lengths = the remaining one (batch = its element count)
    int mask_i = 0;
    for (int i = 1; i < n_in; ++i)
        if (in_sizes[i] > in_sizes[mask_i]) mask_i = i;
    int hn_i = -1, sl_i = -1;
    for (int i = 0; i < n_in; ++i) {
        if (i == mask_i) continue;
        if (in_sizes[i] == 1 && hn_i < 0) hn_i = i;
        else sl_i = i;
    }

    const float* mask = (const float*)d_in[mask_i];
    const int*   sl   = (const int*)d_in[sl_i];
    const int*   hn   = (hn_i >= 0) ? (const int*)d_in[hn_i] : nullptr;
    float* out = (float*)d_out;

    const int batch = in_sizes[sl_i];
    const long long msq = (long long)in_sizes[mask_i] / batch;   // max_seq^2

    // max_seq is a power of two (2048 here); recover it robustly
    int max_seq = 1;
    while ((long long)max_seq * max_seq < msq) max_seq <<= 1;

    setup_kernel<<<1, 1>>>(sl, hn, batch);

    const long long chunks = ((long long)max_seq * max_seq + CHUNK_ELEMS - 1) / CHUNK_ELEMS;
    dim3 block(256);
    dim3 grid((unsigned)(chunks * 8), batch);
    genmask_kernel<<<grid, block>>>(mask, out, max_seq);
}

// round 11
// speedup vs baseline: 2.5025x; 2.5025x over previous
#include <cuda_runtime.h>
#include <cstdint>

// ---------------------------------------------------------------------------
// GenAttentionMask (float32 output: 1.0f / 0.0f):
//   for b in range(batch):
//     s = seq_lengths[b]
//     out += head_num copies of (fp16(mask[b,0,:s,:s]) > 0.5) as float32
//
// fp16_rn(x) > 0.5  <=>  x > 0.500244140625f   (fp16 midpoint, ties-to-even)
//
// R7 memory shape (best measured: 74.2us kernel, 72% DRAM): adjacent lanes own
// adjacent float4s; each thread handles two float4s half a row apart; 16
// fully-covered STG.128 (.cs) per thread. This round: metadata (seq prefix
// sums, head_num) computed inline from gmem instead of a separate setup
// kernel -> one graph node fewer, ~4us less wall time.
// ---------------------------------------------------------------------------

#define THRESH 0.500244140625f

__device__ __forceinline__ float4 thresh4(float4 f) {
    float4 v;
    v.x = (f.x > THRESH) ? 1.0f : 0.0f;
    v.y = (f.y > THRESH) ? 1.0f : 0.0f;
    v.z = (f.z > THRESH) ? 1.0f : 0.0f;
    v.w = (f.w > THRESH) ? 1.0f : 0.0f;
    return v;
}

// One thread: two float4s of one row (cols col and col + s/2), written to all
// head replicas. shift indexes float4-groups per HALF row.
__global__ void __launch_bounds__(256)
genmask_kernel(const float* __restrict__ in, float* __restrict__ out,
               const int* __restrict__ sl, const int* __restrict__ hn_ptr,
               int max_seq, int shift) {
    const int b = blockIdx.y;

    // Inline metadata: s = sl[b]; obase = hn * sum_{i<b} sl[i]^2.
    // <=8 uniform __ldg's, warp-broadcast; amortized over 256B of stores.
    int hn = hn_ptr ? __ldg(hn_ptr) : 8;
    if (hn <= 0 || hn > 64) hn = 8;
    long long acc = 0;
    int s = 0;
#pragma unroll 1
    for (int i = 0; i < b; ++i) {
        int si = __ldg(sl + i);
        acc += (long long)si * si;
    }
    s = __ldg(sl + b);
    const long long obase = acc * hn;

    const int gid = blockIdx.x * blockDim.x + threadIdx.x;
    const int row  = gid >> shift;
    const int col  = (gid & ((1 << shift) - 1)) << 2;   // within first half-row
    const int half = s >> 1;
    if (row >= s || col >= half) return;

    const float* ib = in + (size_t)b * max_seq * max_seq + (size_t)row * max_seq;
    float4 f0 = *reinterpret_cast<const float4*>(ib + col);
    float4 f1 = *reinterpret_cast<const float4*>(ib + half + col);

    float4 v0 = thresh4(f0);
    float4 v1 = thresh4(f1);

    const size_t ss = (size_t)s * (size_t)s;  // head stride (elements)
    float* op = out + (size_t)obase + (size_t)row * s + col;

#pragma unroll 8
    for (int h = 0; h < hn; ++h) {
        __stcs(reinterpret_cast<float4*>(op), v0);
        __stcs(reinterpret_cast<float4*>(op + half), v1);
        op += ss;
    }
}

extern "C" void kernel_launch(void* const* d_in, const int* in_sizes, int n_in,
                              void* d_out, int out_size) {
    // Identify inputs by size, not position:
    //   mask        = largest input
    //   head_num    = 1-element input
    //   seq_lengths = the remaining one (batch = its element count)
    int mask_i = 0;
    for (int i = 1; i < n_in; ++i)
        if (in_sizes[i] > in_sizes[mask_i]) mask_i = i;
    int hn_i = -1, sl_i = -1;
    for (int i = 0; i < n_in; ++i) {
        if (i == mask_i) continue;
        if (in_sizes[i] == 1 && hn_i < 0) hn_i = i;
        else sl_i = i;
    }

    const float* mask = (const float*)d_in[mask_i];
    const int*   sl   = (const int*)d_in[sl_i];
    const int*   hn   = (hn_i >= 0) ? (const int*)d_in[hn_i] : nullptr;
    float* out = (float*)d_out;

    const int batch = in_sizes[sl_i];
    const long long msq = (long long)in_sizes[mask_i] / batch;   // max_seq^2

    // max_seq is a power of two (2048 here); recover it robustly
    int max_seq = 1;
    while ((long long)max_seq * max_seq < msq) max_seq <<= 1;

    // float4-groups per HALF row, padded to a power of two
    const int gpr_pad = max_seq / 8;
    int shift = 0;
    while ((1 << shift) < gpr_pad) ++shift;

    const long long threads_per_batch = (long long)max_seq * gpr_pad;
    dim3 block(256);
    dim3 grid((unsigned)((threads_per_batch + 255) / 256), batch);
    genmask_kernel<<<grid, block>>>(mask, out, sl, hn, max_seq, shift);
}